// round 16
// baseline (speedup 1.0000x reference)
#include <cuda_runtime.h>
#include <cuda_bf16.h>
#include <cuda_fp16.h>
#include <math.h>
#include <stdint.h>

#define TT 64
#define BB 256
#define HH 256
#define VV 10000
#define NPAD 10112   // 79 * 128
#define KK 256       // GEMM K (single fp16 both sides)

// ---------------- scratch (static device globals; no allocation) ----------------
__device__ float g_gx  [(size_t)TT * BB * 3 * HH];   // precomputed x@Wx + b
__device__ float g_hch [(size_t)(TT + 1) * BB * HH]; // h chain
__device__ float g_user[(size_t)BB * VV + 256];      // p_u @ fc_w[H:2H] + fc_b (padded)
__device__ __half g_Ah[(size_t)TT * BB * KK];        // fp16(out_w)  (written by outw_k)
__device__ __half g_Bh[(size_t)NPAD * KK];           // fp16(fc_w^T), K-major

// ---------------- packed f32x2 helpers ----------------
__device__ __forceinline__ unsigned long long pk2(float a) {
    unsigned long long r; unsigned u = __float_as_uint(a);
    asm("mov.b64 %0, {%1, %1};" : "=l"(r) : "r"(u));
    return r;
}
__device__ __forceinline__ void fma2(unsigned long long& d, unsigned long long a, unsigned long long b) {
    asm("fma.rn.f32x2 %0, %1, %2, %0;" : "+l"(d) : "l"(a), "l"(b));
}
__device__ __forceinline__ float2 up2(unsigned long long v) {
    unsigned lo, hi;
    asm("mov.b64 {%0, %1}, %2;" : "=r"(lo), "=r"(hi) : "l"(v));
    float2 r; r.x = __uint_as_float(lo); r.y = __uint_as_float(hi);
    return r;
}

// ---------------- cp.async helpers ----------------
__device__ __forceinline__ void cpa16(float* sdst, const float* gsrc) {
    unsigned s = (unsigned)__cvta_generic_to_shared(sdst);
    asm volatile("cp.async.cg.shared.global [%0], [%1], 16;" :: "r"(s), "l"(gsrc));
}
__device__ __forceinline__ void cpa16u(uint32_t sdst, const void* gsrc) {
    asm volatile("cp.async.cg.shared.global [%0], [%1], 16;" :: "r"(sdst), "l"(gsrc));
}
#define CP_COMMIT() asm volatile("cp.async.commit_group;")
#define CP_WAIT1()  asm volatile("cp.async.wait_group 1;" ::: "memory")
#define CP_WAIT2()  asm volatile("cp.async.wait_group 2;" ::: "memory")
#define CP_WAIT0()  asm volatile("cp.async.wait_group 0;" ::: "memory")

// ---------------- mma.sync helpers (baseline PTX, sm_80+) ----------------
__device__ __forceinline__ void ldsm4(uint32_t& r0, uint32_t& r1, uint32_t& r2, uint32_t& r3, uint32_t addr) {
    asm volatile("ldmatrix.sync.aligned.m8n8.x4.shared.b16 {%0,%1,%2,%3}, [%4];"
        : "=r"(r0), "=r"(r1), "=r"(r2), "=r"(r3) : "r"(addr));
}
__device__ __forceinline__ void mma16816(float* c, uint32_t a0, uint32_t a1, uint32_t a2, uint32_t a3,
                                         uint32_t b0, uint32_t b1) {
    asm volatile("mma.sync.aligned.m16n8k16.row.col.f32.f16.f16.f32 "
        "{%0,%1,%2,%3}, {%4,%5,%6,%7}, {%8,%9}, {%0,%1,%2,%3};"
        : "+f"(c[0]), "+f"(c[1]), "+f"(c[2]), "+f"(c[3])
        : "r"(a0), "r"(a1), "r"(a2), "r"(a3), "r"(b0), "r"(b1));
}

// ================= main projection GEMM: single-pass fp16 mma.sync (R14 config) =================
// C[m][n] = sum_k Ah[m][k] * Bh[n][k] + user[m&255][n]
// CTA 128x128, K=256 (4 ktiles of 64), double-buffered A+B, occupancy 2.
#define MG_NKT  4
#define MGT     16384
#define MG_STG  (2 * MGT)               // A tile + B tile per stage
#define MG_SMEM (2 * MG_STG)            // 64KB

__global__ void __launch_bounds__(256, 2) mgemm_k(const float* __restrict__ user,
                                                  float* __restrict__ C)
{
    extern __shared__ __align__(128) char smem[];
    const int tid  = threadIdx.x;
    const int wid  = tid >> 5, lane = tid & 31;
    const int n0   = blockIdx.x * 128;
    const int m0   = blockIdx.y * 128;
    const int wm   = (wid & 1) * 64;
    const int wn   = (wid >> 1) * 32;
    const uint32_t sb = (uint32_t)__cvta_generic_to_shared(smem);

    const __half* gA = g_Ah + (size_t)m0 * KK;
    const __half* gB = g_Bh + (size_t)n0 * KK;

    const int ldj   = tid & 7;           // 16B chunk within 128B row
    const int ldr0  = tid >> 3;          // base row (0..31)
    const uint32_t ldswz = (uint32_t)(ldj << 4);

    float acc[4][4][4];
    #pragma unroll
    for (int a = 0; a < 4; a++)
        #pragma unroll
        for (int b = 0; b < 4; b++)
            #pragma unroll
            for (int c = 0; c < 4; c++) acc[a][b][c] = 0.f;

    uint32_t aoff[4], axr[4];
    #pragma unroll
    for (int mi = 0; mi < 4; mi++) {
        int row = wm + mi * 16 + (lane & 15);
        aoff[mi] = (uint32_t)row * 128;
        axr[mi]  = (uint32_t)((row & 7) << 4);
    }
    uint32_t boff[2], bxr[2];
    #pragma unroll
    for (int nt = 0; nt < 2; nt++) {
        int row = wn + nt * 16 + (lane & 7) + ((lane >> 3) & 1) * 8;
        boff[nt] = 16384u + (uint32_t)row * 128;
        bxr[nt]  = (uint32_t)((row & 7) << 4);
    }
    const uint32_t chk = (uint32_t)((lane >> 4) << 4);

    // prologue: ktile 0 -> stage 0
    #pragma unroll
    for (int i = 0; i < 4; i++) {
        int row = ldr0 + 32 * i;
        uint32_t swz = ldswz ^ ((uint32_t)(row & 7) << 4);
        cpa16u(sb + (uint32_t)row * 128 + swz,           gA + (size_t)row * KK + ldj * 8);
        cpa16u(sb + 16384u + (uint32_t)row * 128 + swz,  gB + (size_t)row * KK + ldj * 8);
    }
    CP_COMMIT();

    #pragma unroll 1
    for (int kt = 0; kt < MG_NKT; kt++) {
        if (kt + 1 < MG_NKT) {
            int k0 = (kt + 1) * 64;
            uint32_t stb = sb + (uint32_t)((kt + 1) & 1) * MG_STG;
            #pragma unroll
            for (int i = 0; i < 4; i++) {
                int row = ldr0 + 32 * i;
                uint32_t swz = ldswz ^ ((uint32_t)(row & 7) << 4);
                cpa16u(stb + (uint32_t)row * 128 + swz,          gA + (size_t)row * KK + k0 + ldj * 8);
                cpa16u(stb + 16384u + (uint32_t)row * 128 + swz, gB + (size_t)row * KK + k0 + ldj * 8);
            }
            CP_COMMIT();
            CP_WAIT1();
        } else {
            CP_WAIT0();
        }
        __syncthreads();

        const uint32_t stb = sb + (uint32_t)(kt & 1) * MG_STG;
        #pragma unroll
        for (int s = 0; s < 4; s++) {
            const uint32_t inner = (uint32_t)(s * 32) + chk;
            uint32_t a[4][4];
            #pragma unroll
            for (int mi = 0; mi < 4; mi++)
                ldsm4(a[mi][0], a[mi][1], a[mi][2], a[mi][3],
                      stb + aoff[mi] + (inner ^ axr[mi]));
            uint32_t b[2][4];
            #pragma unroll
            for (int nt = 0; nt < 2; nt++)
                ldsm4(b[nt][0], b[nt][1], b[nt][2], b[nt][3],
                      stb + boff[nt] + (inner ^ bxr[nt]));
            #pragma unroll
            for (int mi = 0; mi < 4; mi++) {
                mma16816(acc[mi][0], a[mi][0], a[mi][1], a[mi][2], a[mi][3], b[0][0], b[0][2]);
                mma16816(acc[mi][1], a[mi][0], a[mi][1], a[mi][2], a[mi][3], b[0][1], b[0][3]);
                mma16816(acc[mi][2], a[mi][0], a[mi][1], a[mi][2], a[mi][3], b[1][0], b[1][2]);
                mma16816(acc[mi][3], a[mi][0], a[mi][1], a[mi][2], a[mi][3], b[1][1], b[1][3]);
            }
        }
        __syncthreads();
    }

    // epilogue: + user[m&255][n], store fp32
    const int g = lane >> 2, tg = lane & 3;
    #pragma unroll
    for (int mi = 0; mi < 4; mi++) {
        int mA = m0 + wm + mi * 16 + g;
        int mB = mA + 8;
        const float* uA = user + (size_t)(mA & (BB - 1)) * VV;
        const float* uB = user + (size_t)(mB & (BB - 1)) * VV;
        float* cA = C + (size_t)mA * VV;
        float* cB = C + (size_t)mB * VV;
        #pragma unroll
        for (int ni = 0; ni < 4; ni++) {
            int n = n0 + wn + ni * 8 + tg * 2;
            if (n < VV) {
                float2 u0 = *(const float2*)(uA + n);
                float2 o0 = { acc[mi][ni][0] + u0.x, acc[mi][ni][1] + u0.y };
                *(float2*)(cA + n) = o0;
                float2 u1 = *(const float2*)(uB + n);
                float2 o1 = { acc[mi][ni][2] + u1.x, acc[mi][ni][3] + u1.y };
                *(float2*)(cB + n) = o1;
            }
        }
    }
}

// ---------------- prep: B fp16 transpose ----------------
__global__ void __launch_bounds__(256) prep_B_k(const float* __restrict__ fcw)
{
    __shared__ float ts[32][33];
    const int n0 = blockIdx.x * 32, k0 = blockIdx.y * 32;
    const int tx = threadIdx.x & 31, ty = threadIdx.x >> 5;
    #pragma unroll
    for (int r = 0; r < 32; r += 8) {
        int k = k0 + ty + r, n = n0 + tx;
        ts[ty + r][tx] = (n < VV) ? fcw[(size_t)k * VV + n] : 0.f;
    }
    __syncthreads();
    #pragma unroll
    for (int r = 0; r < 32; r += 8) {
        int n = n0 + ty + r, k = k0 + tx;
        g_Bh[(size_t)n * KK + k] = __float2half(ts[tx][ty + r]);
    }
}

// ---------------- persistent GRU: 3-stage stream pipeline, 2-chunk lookahead ----------------
#define GRU_BS      4
#define GRU_CTAS    (BB / GRU_BS)
#define CHUNK_ROWS  16
#define CACHE_ROWS  16
#define N_STREAM    ((HH - CACHE_ROWS) / CHUNK_ROWS)   // 15
#define NBUF        3
#define GRU_SMEM_FLOATS (CACHE_ROWS*768 + NBUF*CHUNK_ROWS*768 + HH*GRU_BS)
#define GRU_SMEM_BYTES  (GRU_SMEM_FLOATS * 4)          // ~196KB

__global__ void __launch_bounds__(256, 1) gru_all_k(
    const float* __restrict__ wh, const float* __restrict__ h0)
{
    extern __shared__ float smemf[];
    float* whc = smemf;                                  // [16][768] cached rows
    float* buf[NBUF];
    buf[0] = smemf + CACHE_ROWS * 768;
    buf[1] = buf[0] + CHUNK_ROWS * 768;
    buf[2] = buf[1] + CHUNK_ROWS * 768;
    float* hs  = buf[2] + CHUNK_ROWS * 768;              // [256][4]

    const int tid = threadIdx.x;
    const int c   = tid;
    const int b0  = blockIdx.x * GRU_BS;

    for (int i = tid * 4; i < CACHE_ROWS * 768; i += 256 * 4)
        *(float4*)(whc + i) = *(const float4*)(wh + i);

    #pragma unroll
    for (int b = 0; b < GRU_BS; b++)
        hs[c * 4 + b] = h0[(size_t)(b0 + b) * HH + c];
    __syncthreads();

    for (int t = 0; t < TT; t++) {
        float gxr[4], gxz[4], gxn[4];
        #pragma unroll
        for (int b = 0; b < GRU_BS; b++) {
            size_t gi = ((size_t)t * BB + b0 + b) * 768 + c;
            gxr[b] = g_gx[gi];
            gxz[b] = g_gx[gi + 256];
            gxn[b] = g_gx[gi + 512];
        }

        unsigned long long aR0 = 0, aR1 = 0, aZ0 = 0, aZ1 = 0, aN0 = 0, aN1 = 0;

        // prefetch chunks 0 and 1 (rows 16..31, 32..47)
        #pragma unroll
        for (int p = 0; p < 2; p++) {
            const float* src = wh + (size_t)(CACHE_ROWS + p * CHUNK_ROWS) * 768;
            float* dst = buf[p];
            #pragma unroll
            for (int v = 0; v < (CHUNK_ROWS * 768) / (256 * 4); v++) {
                int off = (v * 256 + tid) * 4;
                cpa16(dst + off, src + off);
            }
            CP_COMMIT();
        }

        // compute cached rows (k = 0..15) while chunks stream
        {
            const float* wp = whc;
            #pragma unroll
            for (int kk = 0; kk < CACHE_ROWS; kk++) {
                float wA = wp[kk * 768 + c];
                float wB = wp[kk * 768 + 256 + c];
                float wC = wp[kk * 768 + 512 + c];
                ulonglong2 hv = *(const ulonglong2*)(hs + 4 * kk);
                unsigned long long dA = pk2(wA), dB = pk2(wB), dC = pk2(wC);
                fma2(aR0, dA, hv.x); fma2(aR1, dA, hv.y);
                fma2(aZ0, dB, hv.x); fma2(aZ1, dB, hv.y);
                fma2(aN0, dC, hv.x); fma2(aN1, dC, hv.y);
            }
        }

        // streamed chunks, 2-deep lookahead over 3 buffers
        #pragma unroll 1
        for (int s = 0; s < N_STREAM; s++) {
            __syncthreads();   // all threads done with chunk s-1 (its buffer is reused by s+2)
            if (s + 2 < N_STREAM) {
                const float* src = wh + (size_t)(CACHE_ROWS + (s + 2) * CHUNK_ROWS) * 768;
                float* dst = buf[(s + 2) % NBUF];
                #pragma unroll
                for (int v = 0; v < (CHUNK_ROWS * 768) / (256 * 4); v++) {
                    int off = (v * 256 + tid) * 4;
                    cpa16(dst + off, src + off);
                }
            }
            CP_COMMIT();
            CP_WAIT2();        // chunk s has landed (s+1, s+2 may be pending)
            __syncthreads();
            const float* wp = buf[s % NBUF];
            const int k0 = CACHE_ROWS + s * CHUNK_ROWS;
            #pragma unroll
            for (int kk = 0; kk < CHUNK_ROWS; kk++) {
                float wA = wp[kk * 768 + c];
                float wB = wp[kk * 768 + 256 + c];
                float wC = wp[kk * 768 + 512 + c];
                ulonglong2 hv = *(const ulonglong2*)(hs + 4 * (k0 + kk));
                unsigned long long dA = pk2(wA), dB = pk2(wB), dC = pk2(wC);
                fma2(aR0, dA, hv.x); fma2(aR1, dA, hv.y);
                fma2(aZ0, dB, hv.x); fma2(aZ1, dB, hv.y);
                fma2(aN0, dC, hv.x); fma2(aN1, dC, hv.y);
            }
        }

        float2 vR0 = up2(aR0), vR1 = up2(aR1);
        float2 vZ0 = up2(aZ0), vZ1 = up2(aZ1);
        float2 vN0 = up2(aN0), vN1 = up2(aN1);
        float accR[4] = { vR0.x, vR0.y, vR1.x, vR1.y };
        float accZ[4] = { vZ0.x, vZ0.y, vZ1.x, vZ1.y };
        float accN[4] = { vN0.x, vN0.y, vN1.x, vN1.y };

        float hnew[4];
        #pragma unroll
        for (int b = 0; b < GRU_BS; b++) {
            float rg = 1.f / (1.f + expf(-(gxr[b] + accR[b])));
            float zg = 1.f / (1.f + expf(-(gxz[b] + accZ[b])));
            float ng = tanhf(gxn[b] + rg * accN[b]);
            float hp = hs[c * 4 + b];
            hnew[b] = (1.f - zg) * ng + zg * hp;
            g_hch[((size_t)(t + 1) * BB + b0 + b) * HH + c] = hnew[b];
        }
        __syncthreads();
        *(float4*)(hs + c * 4) = make_float4(hnew[0], hnew[1], hnew[2], hnew[3]);
        __syncthreads();
    }
}

// ---------------- scalar SGEMM (gx and user GEMMs) ----------------
template<bool GATHER_A, bool ADD_USER>
__global__ void __launch_bounds__(256, 2) sgemm_k(
    const float* __restrict__ A, const int* __restrict__ gidx,
    const float* __restrict__ Bmat, const float* __restrict__ bias,
    const float* __restrict__ user, float* __restrict__ C,
    int M, int N, int K, int userB)
{
    __shared__ float As[16][128];
    __shared__ float Bs[16][132];

    const int tid = threadIdx.x;
    const int m0 = blockIdx.y * 128;
    const int n0 = blockIdx.x * 128;
    const int tx = tid & 15, ty = tid >> 4;

    unsigned long long acc[8][4];
    #pragma unroll
    for (int i = 0; i < 8; i++)
        #pragma unroll
        for (int j = 0; j < 4; j++) acc[i][j] = 0ull;

    const int aRow = tid >> 2;
    const int aCol = (tid & 3) << 2;
    const int bRow = tid >> 5;
    const int bCol = (tid & 31) << 2;

    for (int k0 = 0; k0 < K; k0 += 16) {
        #pragma unroll
        for (int r = 0; r < 2; r++) {
            int row = aRow + r * 64;
            size_t ab = GATHER_A ? (size_t)gidx[m0 + row] * K : (size_t)(m0 + row) * K;
            float4 v = *(const float4*)(A + ab + k0 + aCol);
            As[aCol + 0][row] = v.x; As[aCol + 1][row] = v.y;
            As[aCol + 2][row] = v.z; As[aCol + 3][row] = v.w;
        }
        #pragma unroll
        for (int r = 0; r < 2; r++) {
            int krow = k0 + bRow + r * 8;
            int col = n0 + bCol;
            float4 v = make_float4(0.f, 0.f, 0.f, 0.f);
            if (col < N) v = *(const float4*)(Bmat + (size_t)krow * N + col);
            *(float4*)&Bs[bRow + r * 8][bCol] = v;
        }
        __syncthreads();

        #pragma unroll
        for (int k = 0; k < 16; k++) {
            float4 a0 = *(const float4*)&As[k][ty * 8];
            float4 a1 = *(const float4*)&As[k][ty * 8 + 4];
            unsigned long long ra[8];
            ra[0] = pk2(a0.x); ra[1] = pk2(a0.y); ra[2] = pk2(a0.z); ra[3] = pk2(a0.w);
            ra[4] = pk2(a1.x); ra[5] = pk2(a1.y); ra[6] = pk2(a1.z); ra[7] = pk2(a1.w);
            const unsigned long long* bp = (const unsigned long long*)&Bs[k][tx * 8];
            unsigned long long rb[4] = { bp[0], bp[1], bp[2], bp[3] };
            #pragma unroll
            for (int i = 0; i < 8; i++)
                #pragma unroll
                for (int j = 0; j < 4; j++)
                    fma2(acc[i][j], ra[i], rb[j]);
        }
        __syncthreads();
    }

    #pragma unroll
    for (int i = 0; i < 8; i++) {
        int m = m0 + ty * 8 + i;
        const float* ur = ADD_USER ? (user + (size_t)(m & (userB - 1)) * N) : (const float*)0;
        #pragma unroll
        for (int j = 0; j < 4; j++) {
            int n = n0 + tx * 8 + j * 2;
            float2 v = up2(acc[i][j]);
            if (n < N) {
                float o = v.x;
                if (bias) o += bias[n];
                if (ADD_USER) o += ur[n];
                C[(size_t)m * N + n] = o;
            }
            if (n + 1 < N) {
                float o = v.y;
                if (bias) o += bias[n + 1];
                if (ADD_USER) o += ur[n + 1];
                C[(size_t)m * N + n + 1] = o;
            }
        }
    }
}

// ---------------- pairwise spatio-temporal weights + aggregation -> fp16 A ----------------
__global__ void __launch_bounds__(256) outw_k(const float* __restrict__ tin, const float* __restrict__ sin)
{
    __shared__ float st[64];
    __shared__ float ss[128];
    __shared__ float w[64 * 64];
    __shared__ float swi[64];
    __shared__ float oc[64][65];

    const int tid = threadIdx.x;
    const int b = blockIdx.x;

    if (tid < 64)  st[tid] = tin[(size_t)tid * BB + b];
    if (tid < 128) ss[tid] = sin[((size_t)(tid >> 1) * BB + b) * 2 + (tid & 1)];
    __syncthreads();

    const float C1 = 6.283185307179586f / 86400.f;
    const float C2 = 0.1f / 86400.f;

    for (int p = tid; p < 4096; p += 256) {
        int i = p >> 6, j = p & 63;
        float wv = 0.f;
        if (j <= i) {
            float dt = st[i] - st[j];
            float dx = ss[2 * i] - ss[2 * j];
            float dy = ss[2 * i + 1] - ss[2 * j + 1];
            float ds = sqrtf(dx * dx + dy * dy);
            float ft = 0.5f * (cosf(dt * C1) + 1.f) * expf(-dt * C2);
            float fs = expf(-ds * 100.f);
            wv = ft * fs + 1e-10f;
        }
        w[p] = wv;
    }
    __syncthreads();

    if (tid < 64) {
        float s = 0.f;
        #pragma unroll
        for (int j = 0; j < 64; j++) s += w[tid * 64 + j];
        swi[tid] = 1.f / s;
    }
    __syncthreads();

    for (int hc = 0; hc < 256; hc += 64) {
        for (int p = tid; p < 4096; p += 256) {
            int j = p >> 6, hh = p & 63;
            oc[j][hh] = g_hch[((size_t)(j + 1) * BB + b) * HH + hc + hh];
        }
        __syncthreads();
        for (int p = tid; p < 4096; p += 256) {
            int i = p >> 6, hh = p & 63;
            float acc = 0.f;
            #pragma unroll
            for (int j = 0; j < 64; j++) acc += w[i * 64 + j] * oc[j][hh];
            g_Ah[((size_t)i * BB + b) * HH + hc + hh] = __float2half(acc * swi[i]);
        }
        __syncthreads();
    }
}

__global__ void copy_k(const float* __restrict__ src, float* __restrict__ dst, int n)
{
    int i = blockIdx.x * blockDim.x + threadIdx.x;
    if (i < n) dst[i] = src[i];
}

// ---------------- host launcher ----------------
extern "C" void kernel_launch(void* const* d_in, const int* in_sizes, int n_in,
                              void* d_out, int out_size)
{
    const int*   x    = (const int*)  d_in[0];
    const float* tin  = (const float*)d_in[1];
    const float* sin  = (const float*)d_in[2];
    const float* h0   = (const float*)d_in[3];
    const int*   au   = (const int*)  d_in[4];
    const float* poi  = (const float*)d_in[5];
    const float* uemb = (const float*)d_in[6];
    const float* wx   = (const float*)d_in[7];
    const float* wh   = (const float*)d_in[8];
    const float* gb   = (const float*)d_in[9];
    const float* fcw  = (const float*)d_in[10];
    const float* fcb  = (const float*)d_in[11];
    float* out = (float*)d_out;

    float *p_gx, *p_hch, *p_user;
    cudaGetSymbolAddress((void**)&p_gx,   g_gx);
    cudaGetSymbolAddress((void**)&p_hch,  g_hch);
    cudaGetSymbolAddress((void**)&p_user, g_user);

    cudaFuncSetAttribute(gru_all_k, cudaFuncAttributeMaxDynamicSharedMemorySize, GRU_SMEM_BYTES);
    cudaFuncSetAttribute(mgemm_k,   cudaFuncAttributeMaxDynamicSharedMemorySize, MG_SMEM);

    // B -> fp16, transposed (independent of everything else)
    prep_B_k<<<dim3(NPAD / 32, HH / 32), 256>>>(fcw);

    // gx = poi_emb[x] @ Wx + b
    sgemm_k<true, false><<<dim3(6, 128), 256>>>(poi, x, wx, gb, nullptr, p_gx,
                                                TT * BB, 3 * HH, HH, 1);

    // GRU recurrence (persistent, 3-stage pipeline)
    gru_all_k<<<GRU_CTAS, 256, GRU_SMEM_BYTES>>>(wh, h0);

    // spatio-temporal weighted aggregation (writes fp16 A directly)
    outw_k<<<BB, 256>>>(tin, sin);

    // user term: user_emb[active_user] @ fc_w[H:2H] + fc_b
    sgemm_k<true, false><<<dim3(79, 2), 256>>>(uemb, au, fcw + (size_t)HH * VV, fcb,
                                               nullptr, p_user, BB, VV, HH, 1);

    // main projection: single-pass fp16 mma.sync (R14 config)
    mgemm_k<<<dim3(NPAD / 128, TT * BB / 128), 256, MG_SMEM>>>(p_user, out);

    // h_final
    copy_k<<<64, 1024>>>(p_hch + (size_t)TT * BB * HH, out + (size_t)TT * BB * VV, BB * HH);
}

// round 17
// speedup vs baseline: 1.1297x; 1.1297x over previous
#include <cuda_runtime.h>
#include <cuda_bf16.h>
#include <cuda_fp16.h>
#include <math.h>
#include <stdint.h>

#define TT 64
#define BB 256
#define HH 256
#define VV 10000
#define NPAD 10112   // 79 * 128
#define KK 256       // GEMM K (single fp16 both sides)

// ---------------- scratch (static device globals; no allocation) ----------------
__device__ float g_gx  [(size_t)TT * BB * 3 * HH];   // precomputed x@Wx + b
__device__ float g_hch [(size_t)(TT + 1) * BB * HH]; // h chain
__device__ float g_user[(size_t)BB * VV + 256];      // p_u @ fc_w[H:2H] + fc_b (padded)
__device__ __half g_Ah[(size_t)TT * BB * KK];        // fp16(out_w)  (written by outw_k)
__device__ __half g_Bh[(size_t)NPAD * KK];           // fp16(fc_w^T), K-major

// ---------------- packed f32x2 helpers ----------------
__device__ __forceinline__ unsigned long long pk2(float a) {
    unsigned long long r; unsigned u = __float_as_uint(a);
    asm("mov.b64 %0, {%1, %1};" : "=l"(r) : "r"(u));
    return r;
}
__device__ __forceinline__ void fma2(unsigned long long& d, unsigned long long a, unsigned long long b) {
    asm("fma.rn.f32x2 %0, %1, %2, %0;" : "+l"(d) : "l"(a), "l"(b));
}
__device__ __forceinline__ float2 up2(unsigned long long v) {
    unsigned lo, hi;
    asm("mov.b64 {%0, %1}, %2;" : "=r"(lo), "=r"(hi) : "l"(v));
    float2 r; r.x = __uint_as_float(lo); r.y = __uint_as_float(hi);
    return r;
}

// ---------------- cp.async helpers ----------------
__device__ __forceinline__ void cpa16(float* sdst, const float* gsrc) {
    unsigned s = (unsigned)__cvta_generic_to_shared(sdst);
    asm volatile("cp.async.cg.shared.global [%0], [%1], 16;" :: "r"(s), "l"(gsrc));
}
__device__ __forceinline__ void cpa16u(uint32_t sdst, const void* gsrc) {
    asm volatile("cp.async.cg.shared.global [%0], [%1], 16;" :: "r"(sdst), "l"(gsrc));
}
#define CP_COMMIT() asm volatile("cp.async.commit_group;")
#define CP_WAIT1()  asm volatile("cp.async.wait_group 1;" ::: "memory")
#define CP_WAIT0()  asm volatile("cp.async.wait_group 0;" ::: "memory")

// ---------------- mma.sync helpers (baseline PTX, sm_80+) ----------------
__device__ __forceinline__ void ldsm4(uint32_t& r0, uint32_t& r1, uint32_t& r2, uint32_t& r3, uint32_t addr) {
    asm volatile("ldmatrix.sync.aligned.m8n8.x4.shared.b16 {%0,%1,%2,%3}, [%4];"
        : "=r"(r0), "=r"(r1), "=r"(r2), "=r"(r3) : "r"(addr));
}
__device__ __forceinline__ void mma16816(float* c, uint32_t a0, uint32_t a1, uint32_t a2, uint32_t a3,
                                         uint32_t b0, uint32_t b1) {
    asm volatile("mma.sync.aligned.m16n8k16.row.col.f32.f16.f16.f32 "
        "{%0,%1,%2,%3}, {%4,%5,%6,%7}, {%8,%9}, {%0,%1,%2,%3};"
        : "+f"(c[0]), "+f"(c[1]), "+f"(c[2]), "+f"(c[3])
        : "r"(a0), "r"(a1), "r"(a2), "r"(a3), "r"(b0), "r"(b1));
}

// ================= main projection GEMM: single-pass fp16 mma.sync (R14 config) =================
// C[m][n] = sum_k Ah[m][k] * Bh[n][k] + user[m&255][n]
// CTA 128x128, K=256 (4 ktiles of 64), double-buffered A+B, occupancy 2.
#define MG_NKT  4
#define MGT     16384
#define MG_STG  (2 * MGT)               // A tile + B tile per stage
#define MG_SMEM (2 * MG_STG)            // 64KB

__global__ void __launch_bounds__(256, 2) mgemm_k(const float* __restrict__ user,
                                                  float* __restrict__ C)
{
    extern __shared__ __align__(128) char smem[];
    const int tid  = threadIdx.x;
    const int wid  = tid >> 5, lane = tid & 31;
    const int n0   = blockIdx.x * 128;
    const int m0   = blockIdx.y * 128;
    const int wm   = (wid & 1) * 64;
    const int wn   = (wid >> 1) * 32;
    const uint32_t sb = (uint32_t)__cvta_generic_to_shared(smem);

    const __half* gA = g_Ah + (size_t)m0 * KK;
    const __half* gB = g_Bh + (size_t)n0 * KK;

    const int ldj   = tid & 7;           // 16B chunk within 128B row
    const int ldr0  = tid >> 3;          // base row (0..31)
    const uint32_t ldswz = (uint32_t)(ldj << 4);

    float acc[4][4][4];
    #pragma unroll
    for (int a = 0; a < 4; a++)
        #pragma unroll
        for (int b = 0; b < 4; b++)
            #pragma unroll
            for (int c = 0; c < 4; c++) acc[a][b][c] = 0.f;

    uint32_t aoff[4], axr[4];
    #pragma unroll
    for (int mi = 0; mi < 4; mi++) {
        int row = wm + mi * 16 + (lane & 15);
        aoff[mi] = (uint32_t)row * 128;
        axr[mi]  = (uint32_t)((row & 7) << 4);
    }
    uint32_t boff[2], bxr[2];
    #pragma unroll
    for (int nt = 0; nt < 2; nt++) {
        int row = wn + nt * 16 + (lane & 7) + ((lane >> 3) & 1) * 8;
        boff[nt] = 16384u + (uint32_t)row * 128;
        bxr[nt]  = (uint32_t)((row & 7) << 4);
    }
    const uint32_t chk = (uint32_t)((lane >> 4) << 4);

    // prologue: ktile 0 -> stage 0
    #pragma unroll
    for (int i = 0; i < 4; i++) {
        int row = ldr0 + 32 * i;
        uint32_t swz = ldswz ^ ((uint32_t)(row & 7) << 4);
        cpa16u(sb + (uint32_t)row * 128 + swz,           gA + (size_t)row * KK + ldj * 8);
        cpa16u(sb + 16384u + (uint32_t)row * 128 + swz,  gB + (size_t)row * KK + ldj * 8);
    }
    CP_COMMIT();

    #pragma unroll 1
    for (int kt = 0; kt < MG_NKT; kt++) {
        if (kt + 1 < MG_NKT) {
            int k0 = (kt + 1) * 64;
            uint32_t stb = sb + (uint32_t)((kt + 1) & 1) * MG_STG;
            #pragma unroll
            for (int i = 0; i < 4; i++) {
                int row = ldr0 + 32 * i;
                uint32_t swz = ldswz ^ ((uint32_t)(row & 7) << 4);
                cpa16u(stb + (uint32_t)row * 128 + swz,          gA + (size_t)row * KK + k0 + ldj * 8);
                cpa16u(stb + 16384u + (uint32_t)row * 128 + swz, gB + (size_t)row * KK + k0 + ldj * 8);
            }
            CP_COMMIT();
            CP_WAIT1();
        } else {
            CP_WAIT0();
        }
        __syncthreads();

        const uint32_t stb = sb + (uint32_t)(kt & 1) * MG_STG;
        #pragma unroll
        for (int s = 0; s < 4; s++) {
            const uint32_t inner = (uint32_t)(s * 32) + chk;
            uint32_t a[4][4];
            #pragma unroll
            for (int mi = 0; mi < 4; mi++)
                ldsm4(a[mi][0], a[mi][1], a[mi][2], a[mi][3],
                      stb + aoff[mi] + (inner ^ axr[mi]));
            uint32_t b[2][4];
            #pragma unroll
            for (int nt = 0; nt < 2; nt++)
                ldsm4(b[nt][0], b[nt][1], b[nt][2], b[nt][3],
                      stb + boff[nt] + (inner ^ bxr[nt]));
            #pragma unroll
            for (int mi = 0; mi < 4; mi++) {
                mma16816(acc[mi][0], a[mi][0], a[mi][1], a[mi][2], a[mi][3], b[0][0], b[0][2]);
                mma16816(acc[mi][1], a[mi][0], a[mi][1], a[mi][2], a[mi][3], b[0][1], b[0][3]);
                mma16816(acc[mi][2], a[mi][0], a[mi][1], a[mi][2], a[mi][3], b[1][0], b[1][2]);
                mma16816(acc[mi][3], a[mi][0], a[mi][1], a[mi][2], a[mi][3], b[1][1], b[1][3]);
            }
        }
        __syncthreads();
    }

    // epilogue: + user[m&255][n], store fp32
    const int g = lane >> 2, tg = lane & 3;
    #pragma unroll
    for (int mi = 0; mi < 4; mi++) {
        int mA = m0 + wm + mi * 16 + g;
        int mB = mA + 8;
        const float* uA = user + (size_t)(mA & (BB - 1)) * VV;
        const float* uB = user + (size_t)(mB & (BB - 1)) * VV;
        float* cA = C + (size_t)mA * VV;
        float* cB = C + (size_t)mB * VV;
        #pragma unroll
        for (int ni = 0; ni < 4; ni++) {
            int n = n0 + wn + ni * 8 + tg * 2;
            if (n < VV) {
                float2 u0 = *(const float2*)(uA + n);
                float2 o0 = { acc[mi][ni][0] + u0.x, acc[mi][ni][1] + u0.y };
                *(float2*)(cA + n) = o0;
                float2 u1 = *(const float2*)(uB + n);
                float2 o1 = { acc[mi][ni][2] + u1.x, acc[mi][ni][3] + u1.y };
                *(float2*)(cB + n) = o1;
            }
        }
    }
}

// ---------------- prep: B fp16 transpose ----------------
__global__ void __launch_bounds__(256) prep_B_k(const float* __restrict__ fcw)
{
    __shared__ float ts[32][33];
    const int n0 = blockIdx.x * 32, k0 = blockIdx.y * 32;
    const int tx = threadIdx.x & 31, ty = threadIdx.x >> 5;
    #pragma unroll
    for (int r = 0; r < 32; r += 8) {
        int k = k0 + ty + r, n = n0 + tx;
        ts[ty + r][tx] = (n < VV) ? fcw[(size_t)k * VV + n] : 0.f;
    }
    __syncthreads();
    #pragma unroll
    for (int r = 0; r < 32; r += 8) {
        int n = n0 + ty + r, k = k0 + tx;
        g_Bh[(size_t)n * KK + k] = __float2half(ts[tx][ty + r]);
    }
}

// ---------------- persistent GRU (R14 config — known good) ----------------
#define GRU_BS      4
#define GRU_CTAS    (BB / GRU_BS)
#define CHUNK_ROWS  16
#define CACHE_ROWS  32
#define N_STREAM    ((HH - CACHE_ROWS) / CHUNK_ROWS)
#define GRU_SMEM_FLOATS (CACHE_ROWS*768 + 2*CHUNK_ROWS*768 + HH*GRU_BS)
#define GRU_SMEM_BYTES  (GRU_SMEM_FLOATS * 4)

__global__ void __launch_bounds__(256, 1) gru_all_k(
    const float* __restrict__ wh, const float* __restrict__ h0)
{
    extern __shared__ float smemf[];
    float* whc  = smemf;
    float* bufA = smemf + CACHE_ROWS * 768;
    float* bufB = bufA + CHUNK_ROWS * 768;
    float* hs   = bufB + CHUNK_ROWS * 768;

    const int tid = threadIdx.x;
    const int c   = tid;
    const int b0  = blockIdx.x * GRU_BS;

    for (int i = tid * 4; i < CACHE_ROWS * 768; i += 256 * 4)
        *(float4*)(whc + i) = *(const float4*)(wh + i);

    #pragma unroll
    for (int b = 0; b < GRU_BS; b++)
        hs[c * 4 + b] = h0[(size_t)(b0 + b) * HH + c];
    __syncthreads();

    for (int t = 0; t < TT; t++) {
        float gxr[4], gxz[4], gxn[4];
        #pragma unroll
        for (int b = 0; b < GRU_BS; b++) {
            size_t gi = ((size_t)t * BB + b0 + b) * 768 + c;
            gxr[b] = g_gx[gi];
            gxz[b] = g_gx[gi + 256];
            gxn[b] = g_gx[gi + 512];
        }

        unsigned long long aR0 = 0, aR1 = 0, aZ0 = 0, aZ1 = 0, aN0 = 0, aN1 = 0;

        {
            const float* src = wh + (size_t)CACHE_ROWS * 768;
            #pragma unroll
            for (int v = 0; v < (CHUNK_ROWS * 768) / (256 * 4); v++) {
                int off = (v * 256 + tid) * 4;
                cpa16(bufA + off, src + off);
            }
            CP_COMMIT();
        }

        #pragma unroll 1
        for (int cc = 0; cc < CACHE_ROWS / CHUNK_ROWS; cc++) {
            const float* wp = whc + cc * CHUNK_ROWS * 768;
            const int k0 = cc * CHUNK_ROWS;
            #pragma unroll
            for (int kk = 0; kk < CHUNK_ROWS; kk++) {
                float wA = wp[kk * 768 + c];
                float wB = wp[kk * 768 + 256 + c];
                float wC = wp[kk * 768 + 512 + c];
                ulonglong2 hv = *(const ulonglong2*)(hs + 4 * (k0 + kk));
                unsigned long long dA = pk2(wA), dB = pk2(wB), dC = pk2(wC);
                fma2(aR0, dA, hv.x); fma2(aR1, dA, hv.y);
                fma2(aZ0, dB, hv.x); fma2(aZ1, dB, hv.y);
                fma2(aN0, dC, hv.x); fma2(aN1, dC, hv.y);
            }
        }

        int buf = 0;
        #pragma unroll 1
        for (int s = 0; s < N_STREAM; s++) {
            __syncthreads();
            if (s + 1 < N_STREAM) {
                const float* src = wh + (size_t)(CACHE_ROWS + (s + 1) * CHUNK_ROWS) * 768;
                float* dst = (buf ? bufA : bufB);
                #pragma unroll
                for (int v = 0; v < (CHUNK_ROWS * 768) / (256 * 4); v++) {
                    int off = (v * 256 + tid) * 4;
                    cpa16(dst + off, src + off);
                }
            }
            CP_COMMIT();
            CP_WAIT1();
            __syncthreads();
            const float* wp = (buf ? bufB : bufA);
            const int k0 = CACHE_ROWS + s * CHUNK_ROWS;
            #pragma unroll
            for (int kk = 0; kk < CHUNK_ROWS; kk++) {
                float wA = wp[kk * 768 + c];
                float wB = wp[kk * 768 + 256 + c];
                float wC = wp[kk * 768 + 512 + c];
                ulonglong2 hv = *(const ulonglong2*)(hs + 4 * (k0 + kk));
                unsigned long long dA = pk2(wA), dB = pk2(wB), dC = pk2(wC);
                fma2(aR0, dA, hv.x); fma2(aR1, dA, hv.y);
                fma2(aZ0, dB, hv.x); fma2(aZ1, dB, hv.y);
                fma2(aN0, dC, hv.x); fma2(aN1, dC, hv.y);
            }
            buf ^= 1;
        }

        float2 vR0 = up2(aR0), vR1 = up2(aR1);
        float2 vZ0 = up2(aZ0), vZ1 = up2(aZ1);
        float2 vN0 = up2(aN0), vN1 = up2(aN1);
        float accR[4] = { vR0.x, vR0.y, vR1.x, vR1.y };
        float accZ[4] = { vZ0.x, vZ0.y, vZ1.x, vZ1.y };
        float accN[4] = { vN0.x, vN0.y, vN1.x, vN1.y };

        float hnew[4];
        #pragma unroll
        for (int b = 0; b < GRU_BS; b++) {
            float rg = 1.f / (1.f + expf(-(gxr[b] + accR[b])));
            float zg = 1.f / (1.f + expf(-(gxz[b] + accZ[b])));
            float ng = tanhf(gxn[b] + rg * accN[b]);
            float hp = hs[c * 4 + b];
            hnew[b] = (1.f - zg) * ng + zg * hp;
            g_hch[((size_t)(t + 1) * BB + b0 + b) * HH + c] = hnew[b];
        }
        __syncthreads();
        *(float4*)(hs + c * 4) = make_float4(hnew[0], hnew[1], hnew[2], hnew[3]);
        __syncthreads();
    }
}

// ---------------- scalar SGEMM (gx and user GEMMs) ----------------
template<bool GATHER_A, bool ADD_USER>
__global__ void __launch_bounds__(256, 2) sgemm_k(
    const float* __restrict__ A, const int* __restrict__ gidx,
    const float* __restrict__ Bmat, const float* __restrict__ bias,
    const float* __restrict__ user, float* __restrict__ C,
    int M, int N, int K, int userB)
{
    __shared__ float As[16][128];
    __shared__ float Bs[16][132];

    const int tid = threadIdx.x;
    const int m0 = blockIdx.y * 128;
    const int n0 = blockIdx.x * 128;
    const int tx = tid & 15, ty = tid >> 4;

    unsigned long long acc[8][4];
    #pragma unroll
    for (int i = 0; i < 8; i++)
        #pragma unroll
        for (int j = 0; j < 4; j++) acc[i][j] = 0ull;

    const int aRow = tid >> 2;
    const int aCol = (tid & 3) << 2;
    const int bRow = tid >> 5;
    const int bCol = (tid & 31) << 2;

    for (int k0 = 0; k0 < K; k0 += 16) {
        #pragma unroll
        for (int r = 0; r < 2; r++) {
            int row = aRow + r * 64;
            size_t ab = GATHER_A ? (size_t)gidx[m0 + row] * K : (size_t)(m0 + row) * K;
            float4 v = *(const float4*)(A + ab + k0 + aCol);
            As[aCol + 0][row] = v.x; As[aCol + 1][row] = v.y;
            As[aCol + 2][row] = v.z; As[aCol + 3][row] = v.w;
        }
        #pragma unroll
        for (int r = 0; r < 2; r++) {
            int krow = k0 + bRow + r * 8;
            int col = n0 + bCol;
            float4 v = make_float4(0.f, 0.f, 0.f, 0.f);
            if (col < N) v = *(const float4*)(Bmat + (size_t)krow * N + col);
            *(float4*)&Bs[bRow + r * 8][bCol] = v;
        }
        __syncthreads();

        #pragma unroll
        for (int k = 0; k < 16; k++) {
            float4 a0 = *(const float4*)&As[k][ty * 8];
            float4 a1 = *(const float4*)&As[k][ty * 8 + 4];
            unsigned long long ra[8];
            ra[0] = pk2(a0.x); ra[1] = pk2(a0.y); ra[2] = pk2(a0.z); ra[3] = pk2(a0.w);
            ra[4] = pk2(a1.x); ra[5] = pk2(a1.y); ra[6] = pk2(a1.z); ra[7] = pk2(a1.w);
            const unsigned long long* bp = (const unsigned long long*)&Bs[k][tx * 8];
            unsigned long long rb[4] = { bp[0], bp[1], bp[2], bp[3] };
            #pragma unroll
            for (int i = 0; i < 8; i++)
                #pragma unroll
                for (int j = 0; j < 4; j++)
                    fma2(acc[i][j], ra[i], rb[j]);
        }
        __syncthreads();
    }

    #pragma unroll
    for (int i = 0; i < 8; i++) {
        int m = m0 + ty * 8 + i;
        const float* ur = ADD_USER ? (user + (size_t)(m & (userB - 1)) * N) : (const float*)0;
        #pragma unroll
        for (int j = 0; j < 4; j++) {
            int n = n0 + tx * 8 + j * 2;
            float2 v = up2(acc[i][j]);
            if (n < N) {
                float o = v.x;
                if (bias) o += bias[n];
                if (ADD_USER) o += ur[n];
                C[(size_t)m * N + n] = o;
            }
            if (n + 1 < N) {
                float o = v.y;
                if (bias) o += bias[n + 1];
                if (ADD_USER) o += ur[n + 1];
                C[(size_t)m * N + n + 1] = o;
            }
        }
    }
}

// ---------------- pairwise spatio-temporal weights + aggregation -> fp16 A ----------------
__global__ void __launch_bounds__(256) outw_k(const float* __restrict__ tin, const float* __restrict__ sin)
{
    __shared__ float st[64];
    __shared__ float ss[128];
    __shared__ float w[64 * 64];
    __shared__ float swi[64];
    __shared__ float oc[64][65];

    const int tid = threadIdx.x;
    const int b = blockIdx.x;

    if (tid < 64)  st[tid] = tin[(size_t)tid * BB + b];
    if (tid < 128) ss[tid] = sin[((size_t)(tid >> 1) * BB + b) * 2 + (tid & 1)];
    __syncthreads();

    const float C1 = 6.283185307179586f / 86400.f;
    const float C2 = 0.1f / 86400.f;

    for (int p = tid; p < 4096; p += 256) {
        int i = p >> 6, j = p & 63;
        float wv = 0.f;
        if (j <= i) {
            float dt = st[i] - st[j];
            float dx = ss[2 * i] - ss[2 * j];
            float dy = ss[2 * i + 1] - ss[2 * j + 1];
            float ds = sqrtf(dx * dx + dy * dy);
            float ft = 0.5f * (cosf(dt * C1) + 1.f) * expf(-dt * C2);
            float fs = expf(-ds * 100.f);
            wv = ft * fs + 1e-10f;
        }
        w[p] = wv;
    }
    __syncthreads();

    if (tid < 64) {
        float s = 0.f;
        #pragma unroll
        for (int j = 0; j < 64; j++) s += w[tid * 64 + j];
        swi[tid] = 1.f / s;
    }
    __syncthreads();

    for (int hc = 0; hc < 256; hc += 64) {
        for (int p = tid; p < 4096; p += 256) {
            int j = p >> 6, hh = p & 63;
            oc[j][hh] = g_hch[((size_t)(j + 1) * BB + b) * HH + hc + hh];
        }
        __syncthreads();
        for (int p = tid; p < 4096; p += 256) {
            int i = p >> 6, hh = p & 63;
            float acc = 0.f;
            #pragma unroll
            for (int j = 0; j < 64; j++) acc += w[i * 64 + j] * oc[j][hh];
            g_Ah[((size_t)i * BB + b) * HH + hc + hh] = __float2half(acc * swi[i]);
        }
        __syncthreads();
    }
}

__global__ void copy_k(const float* __restrict__ src, float* __restrict__ dst, int n)
{
    int i = blockIdx.x * blockDim.x + threadIdx.x;
    if (i < n) dst[i] = src[i];
}

// ---------------- host launcher ----------------
extern "C" void kernel_launch(void* const* d_in, const int* in_sizes, int n_in,
                              void* d_out, int out_size)
{
    const int*   x    = (const int*)  d_in[0];
    const float* tin  = (const float*)d_in[1];
    const float* sin  = (const float*)d_in[2];
    const float* h0   = (const float*)d_in[3];
    const int*   au   = (const int*)  d_in[4];
    const float* poi  = (const float*)d_in[5];
    const float* uemb = (const float*)d_in[6];
    const float* wx   = (const float*)d_in[7];
    const float* wh   = (const float*)d_in[8];
    const float* gb   = (const float*)d_in[9];
    const float* fcw  = (const float*)d_in[10];
    const float* fcb  = (const float*)d_in[11];
    float* out = (float*)d_out;

    float *p_gx, *p_hch, *p_user;
    cudaGetSymbolAddress((void**)&p_gx,   g_gx);
    cudaGetSymbolAddress((void**)&p_hch,  g_hch);
    cudaGetSymbolAddress((void**)&p_user, g_user);

    cudaFuncSetAttribute(gru_all_k, cudaFuncAttributeMaxDynamicSharedMemorySize, GRU_SMEM_BYTES);
    cudaFuncSetAttribute(mgemm_k,   cudaFuncAttributeMaxDynamicSharedMemorySize, MG_SMEM);

    // B -> fp16, transposed (independent of everything else)
    prep_B_k<<<dim3(NPAD / 32, HH / 32), 256>>>(fcw);

    // gx = poi_emb[x] @ Wx + b
    sgemm_k<true, false><<<dim3(6, 128), 256>>>(poi, x, wx, gb, nullptr, p_gx,
                                                TT * BB, 3 * HH, HH, 1);

    // GRU recurrence (persistent, R14 config)
    gru_all_k<<<GRU_CTAS, 256, GRU_SMEM_BYTES>>>(wh, h0);

    // spatio-temporal weighted aggregation (writes fp16 A directly)
    outw_k<<<BB, 256>>>(tin, sin);

    // user term: user_emb[active_user] @ fc_w[H:2H] + fc_b
    sgemm_k<true, false><<<dim3(79, 2), 256>>>(uemb, au, fcw + (size_t)HH * VV, fcb,
                                               nullptr, p_user, BB, VV, HH, 1);

    // main projection: single-pass fp16 mma.sync (R14 config)
    mgemm_k<<<dim3(NPAD / 128, TT * BB / 128), 256, MG_SMEM>>>(p_user, out);

    // h_final
    copy_k<<<64, 1024>>>(p_hch + (size_t)TT * BB * HH, out + (size_t)TT * BB * VV, BB * HH);
}